// round 11
// baseline (speedup 1.0000x reference)
#include <cuda_runtime.h>
#include <cuda_bf16.h>

#define NN 8192
#define IN_N 1024
#define OUT_N 256

#define S_FULL 128           // row splits for full gemv  (64 rows each)
#define S_IN   128           // row splits for input gemv (8 rows each)
#define S_OUT  256           // row splits for last-cols gemv (32 rows each)

// scratch (no allocation allowed): three s vectors, zeroed each call
__device__ float g_s[3][NN];

// ---------------------------------------------------------------------------
// zero the accumulator vectors and the output
// ---------------------------------------------------------------------------
__global__ __launch_bounds__(256) void zero_accum(float* __restrict__ s,
                                                  float* __restrict__ out)
{
    const int i = blockIdx.x * blockDim.x + threadIdx.x;
    if (i < 3 * NN) s[i] = 0.f;
    if (i < OUT_N)  out[i] = 0.f;
}

// ---------------------------------------------------------------------------
// s_out[j] += sum_i W[i, j] * v[i]  over rows [row_begin + split*rps, +rps)
// each thread owns 4 consecutive columns via float4 (coalesced 128B/warp/row),
// accumulates in registers, then 4 spread-address atomicAdds (REDG).
// grid: (NN/1024, n_splits), block: 256
// ---------------------------------------------------------------------------
__global__ __launch_bounds__(256) void gemvT_atomic(
    const float* __restrict__ W, const float* __restrict__ v,
    float* __restrict__ s_out, int row_begin, int rows_per_split)
{
    const int split = blockIdx.y;
    const int c4 = blockIdx.x * blockDim.x + threadIdx.x;   // float4 column index
    const int r0 = row_begin + split * rows_per_split;

    const float4* __restrict__ W4 = reinterpret_cast<const float4*>(W);

    float ax = 0.f, ay = 0.f, az = 0.f, aw = 0.f;

    for (int i = 0; i < rows_per_split; i += 4) {
#pragma unroll
        for (int u = 0; u < 4; u++) {
            const int r = r0 + i + u;
            const float sv = __ldg(&v[r]);
            const float4 w = __ldcs(&W4[(size_t)r * (NN / 4) + c4]);  // streaming: evict-first
            ax = fmaf(w.x, sv, ax);
            ay = fmaf(w.y, sv, ay);
            az = fmaf(w.z, sv, az);
            aw = fmaf(w.w, sv, aw);
        }
    }

    float* dst = s_out + 4 * c4;
    atomicAdd(dst + 0, ax);
    atomicAdd(dst + 1, ay);
    atomicAdd(dst + 2, az);
    atomicAdd(dst + 3, aw);
}

// ---------------------------------------------------------------------------
// last-256-columns gemv fused with diagonal scale:
//   out[j] += W[d,d] * sum_{i in split} W[i, NN-256+j] * v[i],  d = NN-256+j
// ---------------------------------------------------------------------------
__global__ __launch_bounds__(256) void gemvT_lastcols_atomic(
    const float* __restrict__ W, const float* __restrict__ v,
    float* __restrict__ out, int rows_per_split)
{
    const int split = blockIdx.x;
    const int j = threadIdx.x;                 // 0..255
    const int colg = NN - OUT_N + j;
    const int r0 = split * rows_per_split;

    float acc = 0.f;
#pragma unroll 4
    for (int i = 0; i < rows_per_split; i++) {
        const int r = r0 + i;
        acc = fmaf(__ldg(&W[(size_t)r * NN + colg]), __ldg(&v[r]), acc);
    }

    const float wdd = __ldg(&W[(size_t)colg * NN + colg]);
    atomicAdd(&out[j], wdd * acc);
}

extern "C" void kernel_launch(void* const* d_in, const int* in_sizes, int n_in,
                              void* d_out, int out_size)
{
    // identify inputs by size (robust to ordering): x=1024, W=8192*8192
    const float* x = nullptr;
    const float* W = nullptr;
    for (int i = 0; i < n_in; i++) {
        if (in_sizes[i] == IN_N) x = (const float*)d_in[i];
        else if (in_sizes[i] == NN * NN) W = (const float*)d_in[i];
    }
    if (!x) x = (const float*)d_in[0];
    if (!W) W = (const float*)d_in[1];
    float* out = (float*)d_out;

    float* sbase; cudaGetSymbolAddress((void**)&sbase, g_s);
    float* s1 = sbase;            // g_s[0]
    float* s2 = sbase + NN;       // g_s[1]
    float* s3 = sbase + 2 * NN;   // g_s[2]

    const dim3 blk(256);

    // zero accumulators + out (must precede all atomics; stream serializes)
    zero_accum<<<(3 * NN + 255) / 256, blk>>>(sbase, out);

    // step 1: s1 = W[0:1024,:]^T x   (s0 zero outside first 1024 rows)
    gemvT_atomic<<<dim3(NN / 1024, S_IN), blk>>>(W, x, s1, 0, IN_N / S_IN);     // 8 rows/split

    // step 2: s2 = W^T s1   (full matrix, 268 MB)
    gemvT_atomic<<<dim3(NN / 1024, S_FULL), blk>>>(W, s1, s2, 0, NN / S_FULL);  // 64 rows/split

    // step 3: s3 = W^T s2   (full matrix, 268 MB)
    gemvT_atomic<<<dim3(NN / 1024, S_FULL), blk>>>(W, s2, s3, 0, NN / S_FULL);

    // step 4: out[j] = W[d,d] * (W^T s3)[d] over last 256 columns, fused scale
    gemvT_lastcols_atomic<<<S_OUT, blk>>>(W, s3, out, NN / S_OUT);              // 32 rows/split
}

// round 14
// speedup vs baseline: 1.1095x; 1.1095x over previous
#include <cuda_runtime.h>
#include <cuda_bf16.h>

#define NN 8192
#define IN_N 1024
#define OUT_N 256

#define S_FULL 64            // row splits for full gemv  (128 rows each)
#define S_IN   64            // row splits for input gemv (16 rows each)
#define S_OUT  256           // row splits for last-cols gemv (32 rows each)

// scratch (no allocation allowed): three s vectors, zeroed each call
__device__ float g_s[3][NN];

// ---------------------------------------------------------------------------
// zero the accumulator vectors and the output
// ---------------------------------------------------------------------------
__global__ __launch_bounds__(256) void zero_accum(float* __restrict__ s,
                                                  float* __restrict__ out)
{
    const int i = blockIdx.x * blockDim.x + threadIdx.x;
    if (i < 3 * NN) s[i] = 0.f;
    if (i < OUT_N)  out[i] = 0.f;
}

// ---------------------------------------------------------------------------
// s_out[j] += sum_i W[i, j] * v[i]  over rows [split*rps, split*rps+rps)
// each thread owns 4 consecutive columns via float4 (coalesced 128B/warp/row),
// accumulates in registers, then 4 spread-address atomicAdds (REDG).
// DESC=1 walks the split's rows descending: first touches the lines the
// previous (ascending) pass read LAST -> they are still L2-resident.
// grid: (NN/1024, n_splits), block: 256
// ---------------------------------------------------------------------------
template <int DESC>
__global__ __launch_bounds__(256) void gemvT_atomic(
    const float* __restrict__ W, const float* __restrict__ v,
    float* __restrict__ s_out, int rows_per_split)
{
    const int split = blockIdx.y;
    const int c4 = blockIdx.x * blockDim.x + threadIdx.x;   // float4 column index
    const int r0 = split * rows_per_split;

    const float4* __restrict__ W4 = reinterpret_cast<const float4*>(W);

    float ax = 0.f, ay = 0.f, az = 0.f, aw = 0.f;

    for (int i = 0; i < rows_per_split; i += 4) {
        const int ib = DESC ? (rows_per_split - 4 - i) : i;
#pragma unroll
        for (int u = 0; u < 4; u++) {
            const int r = r0 + ib + u;
            const float sv = __ldg(&v[r]);
            const float4 w = __ldg(&W4[(size_t)r * (NN / 4) + c4]);
            ax = fmaf(w.x, sv, ax);
            ay = fmaf(w.y, sv, ay);
            az = fmaf(w.z, sv, az);
            aw = fmaf(w.w, sv, aw);
        }
    }

    float* dst = s_out + 4 * c4;
    atomicAdd(dst + 0, ax);
    atomicAdd(dst + 1, ay);
    atomicAdd(dst + 2, az);
    atomicAdd(dst + 3, aw);
}

// ---------------------------------------------------------------------------
// last-256-columns gemv fused with diagonal scale:
//   out[j] += W[d,d] * sum_{i in split} W[i, NN-256+j] * v[i],  d = NN-256+j
// descending rows: step3 finished on LOW rows, so low rows are L2-resident;
// but step3's residency covers per-split tails -> order here is minor, keep
// ascending-within-split, whole thing is only 8 MB.
// ---------------------------------------------------------------------------
__global__ __launch_bounds__(256) void gemvT_lastcols_atomic(
    const float* __restrict__ W, const float* __restrict__ v,
    float* __restrict__ out, int rows_per_split)
{
    const int split = blockIdx.x;
    const int j = threadIdx.x;                 // 0..255
    const int colg = NN - OUT_N + j;
    const int r0 = split * rows_per_split;

    float acc = 0.f;
#pragma unroll 4
    for (int i = 0; i < rows_per_split; i++) {
        const int r = r0 + i;
        acc = fmaf(__ldg(&W[(size_t)r * NN + colg]), __ldg(&v[r]), acc);
    }

    const float wdd = __ldg(&W[(size_t)colg * NN + colg]);
    atomicAdd(&out[j], wdd * acc);
}

extern "C" void kernel_launch(void* const* d_in, const int* in_sizes, int n_in,
                              void* d_out, int out_size)
{
    // identify inputs by size (robust to ordering): x=1024, W=8192*8192
    const float* x = nullptr;
    const float* W = nullptr;
    for (int i = 0; i < n_in; i++) {
        if (in_sizes[i] == IN_N) x = (const float*)d_in[i];
        else if (in_sizes[i] == NN * NN) W = (const float*)d_in[i];
    }
    if (!x) x = (const float*)d_in[0];
    if (!W) W = (const float*)d_in[1];
    float* out = (float*)d_out;

    float* sbase; cudaGetSymbolAddress((void**)&sbase, g_s);
    float* s1 = sbase;            // g_s[0]
    float* s2 = sbase + NN;       // g_s[1]
    float* s3 = sbase + 2 * NN;   // g_s[2]

    const dim3 blk(256);

    // zero accumulators + out (must precede all atomics; stream serializes)
    zero_accum<<<(3 * NN + 255) / 256, blk>>>(sbase, out);

    // step 1: s1 = W[0:1024,:]^T x  -- 32 MB, fully fits L2, read ascending
    // (splits cover rows 0..1023 only: 64 splits x 16 rows)
    gemvT_atomic<0><<<dim3(NN / 1024, S_IN), blk>>>(W, x, s1, IN_N / S_IN);

    // step 2: s2 = W^T s1  (full 268 MB) ASCENDING:
    //   - rows 0..1023 hit L2 (left by step 1)
    //   - leaves the tail of each 128-row split resident for step 3
    gemvT_atomic<0><<<dim3(NN / 1024, S_FULL), blk>>>(W, s1, s2, NN / S_FULL);

    // step 3: s3 = W^T s2  (full 268 MB) DESCENDING within each split:
    //   first reads are step 2's most-recent lines -> ~120 MB L2 hits
    gemvT_atomic<1><<<dim3(NN / 1024, S_FULL), blk>>>(W, s2, s3, NN / S_FULL);

    // step 4: out[j] = W[d,d] * (W^T s3)[d] over last 256 columns, fused scale
    gemvT_lastcols_atomic<<<S_OUT, blk>>>(W, s3, out, NN / S_OUT);
}